// round 10
// baseline (speedup 1.0000x reference)
#include <cuda_runtime.h>
#include <cuda_bf16.h>
#include <cstdint>

// ---------------------------------------------------------------------------
// GNN_85366769975686  (R9: 2-stream DAG, split GEMM2, un-fused fill)
//   layer(feat, W, b): m = feat@W + b ; agg = segment_sum(m[src], dst)
//                      return concat([agg, m], -1)
// N = 50000 nodes, E = 800000 edges, D = 128, output [N, 256] fp32.
// GEMM: 3x-bf16-split m16n8k16 mma.sync (tcgen05 unusable at compute_103).
// DAG: prep -> { gemm1 -> gemm2_m (s0) } || { hist -> scan -> fill (s2) }
//      -> gather1 -> gemm2_agg -> gather2
// ---------------------------------------------------------------------------

#define N_MAX     50048
#define E_MAX     800000
#define LDC       256
#define SCAN_B    256
#define SCAN_GRID ((N_MAX + SCAN_B - 1) / SCAN_B)   // 196

__device__ float g_feat1[(size_t)N_MAX * LDC];
__device__ int   g_cnt[N_MAX + 1];
__device__ int   g_row_start[N_MAX + 1];
__device__ int   g_cursor[N_MAX + 1];
__device__ int   g_edge_src[E_MAX];
__device__ unsigned long long g_scan_state[SCAN_GRID];
// W split into bf16 hi/lo, packed bf16x2 along K, layout [n=128][K/2 words]
__device__ uint32_t g_B1hi[128 * 64];
__device__ uint32_t g_B1lo[128 * 64];
__device__ uint32_t g_B2hi[128 * 128];
__device__ uint32_t g_B2lo[128 * 128];

// ---------------------------------------------------------------------------
__device__ __forceinline__ uint32_t pack_bf16x2(__nv_bfloat16 lo, __nv_bfloat16 hi) {
    __nv_bfloat162 t = __halves2bfloat162(lo, hi);
    return *reinterpret_cast<uint32_t*>(&t);
}

__device__ __forceinline__ void mma_bf16(float* d, const uint32_t* a,
                                         const uint32_t b0, const uint32_t b1) {
    asm volatile(
        "mma.sync.aligned.m16n8k16.row.col.f32.bf16.bf16.f32 "
        "{%0,%1,%2,%3}, {%4,%5,%6,%7}, {%8,%9}, {%0,%1,%2,%3};"
        : "+f"(d[0]), "+f"(d[1]), "+f"(d[2]), "+f"(d[3])
        : "r"(a[0]), "r"(a[1]), "r"(a[2]), "r"(a[3]), "r"(b0), "r"(b1));
}

// ---------------------------------------------------------------------------
// GEMM: C[row, 128+col] (+)= sum_k A[row,k]*B[k,col]  (+ bias if bias != null)
//   A: fp32 [.., lda]; B: bf16x2 hi/lo, row stride bKw words
//   bias == nullptr -> accumulate into existing C (no bias)
// Tile 128x128, K-chunk 32; warps 4(M)x2(N); m16n8k16; APAD=20 conflict-free.
// ---------------------------------------------------------------------------
#define APAD 20
#define SM_AHI 0
#define SM_ALO (128 * APAD)
#define SM_BHI (2 * 128 * APAD)
#define SM_BLO (3 * 128 * APAD)

__global__ __launch_bounds__(256)
void gemm_tc(const float* __restrict__ A, int lda,
             const uint32_t* __restrict__ Bhi, const uint32_t* __restrict__ Blo,
             int bKw,
             const float* __restrict__ bias,
             float* __restrict__ C, int M, int K)
{
    __shared__ uint32_t sm[4 * 128 * APAD];   // 40 KB

    const int tid  = threadIdx.x;
    const int wid  = tid >> 5;
    const int lane = tid & 31;
    const int g    = lane >> 2;
    const int tg   = lane & 3;
    const int wm   = wid & 3;
    const int wn   = wid >> 2;
    const int row0 = blockIdx.x * 128;

    float d[2][8][4];
#pragma unroll
    for (int i = 0; i < 2; i++)
#pragma unroll
        for (int j = 0; j < 8; j++)
#pragma unroll
            for (int c = 0; c < 4; c++) d[i][j][c] = 0.0f;

    const int nch = K >> 5;
    for (int kc = 0; kc < nch; kc++) {
#pragma unroll
        for (int l = 0; l < 4; l++) {
            int idx = tid + l * 256;
            int row = idx >> 3;
            int c4  = idx & 7;
            int wo  = row * APAD + c4 * 2;

            int gr = row0 + row;
            float4 v = make_float4(0.f, 0.f, 0.f, 0.f);
            if (gr < M)
                v = *reinterpret_cast<const float4*>(A + (size_t)gr * lda + kc * 32 + c4 * 4);
            __nv_bfloat16 hx = __float2bfloat16_rn(v.x);
            __nv_bfloat16 hy = __float2bfloat16_rn(v.y);
            __nv_bfloat16 hz = __float2bfloat16_rn(v.z);
            __nv_bfloat16 hw = __float2bfloat16_rn(v.w);
            uint2 hv, lv;
            hv.x = pack_bf16x2(hx, hy);
            hv.y = pack_bf16x2(hz, hw);
            lv.x = pack_bf16x2(__float2bfloat16_rn(v.x - __bfloat162float(hx)),
                               __float2bfloat16_rn(v.y - __bfloat162float(hy)));
            lv.y = pack_bf16x2(__float2bfloat16_rn(v.z - __bfloat162float(hz)),
                               __float2bfloat16_rn(v.w - __bfloat162float(hw)));
            *reinterpret_cast<uint2*>(sm + SM_AHI + wo) = hv;
            *reinterpret_cast<uint2*>(sm + SM_ALO + wo) = lv;

            const size_t bofs = (size_t)row * bKw + kc * 16 + c4 * 2;
            *reinterpret_cast<uint2*>(sm + SM_BHI + wo) =
                *reinterpret_cast<const uint2*>(Bhi + bofs);
            *reinterpret_cast<uint2*>(sm + SM_BLO + wo) =
                *reinterpret_cast<const uint2*>(Blo + bofs);
        }
        __syncthreads();

#pragma unroll
        for (int ks = 0; ks < 2; ks++) {
            const int kk = ks * 8;
            uint32_t ah[2][4], al[2][4];
#pragma unroll
            for (int mf = 0; mf < 2; mf++) {
                int r0 = (wm * 32 + mf * 16 + g) * APAD + kk + tg;
                int r8 = r0 + 8 * APAD;
                ah[mf][0] = sm[SM_AHI + r0];
                ah[mf][1] = sm[SM_AHI + r8];
                ah[mf][2] = sm[SM_AHI + r0 + 4];
                ah[mf][3] = sm[SM_AHI + r8 + 4];
                al[mf][0] = sm[SM_ALO + r0];
                al[mf][1] = sm[SM_ALO + r8];
                al[mf][2] = sm[SM_ALO + r0 + 4];
                al[mf][3] = sm[SM_ALO + r8 + 4];
            }
#pragma unroll
            for (int nf = 0; nf < 8; nf++) {
                int bo = (wn * 64 + nf * 8 + g) * APAD + kk + tg;
                uint32_t bh0 = sm[SM_BHI + bo];
                uint32_t bh1 = sm[SM_BHI + bo + 4];
                uint32_t bl0 = sm[SM_BLO + bo];
                uint32_t bl1 = sm[SM_BLO + bo + 4];
#pragma unroll
                for (int mf = 0; mf < 2; mf++) {
                    mma_bf16(d[mf][nf], ah[mf], bh0, bh1);
                    mma_bf16(d[mf][nf], al[mf], bh0, bh1);
                    mma_bf16(d[mf][nf], ah[mf], bl0, bl1);
                }
            }
        }
        __syncthreads();
    }

    const bool add_bias = (bias != nullptr);
#pragma unroll
    for (int nf = 0; nf < 8; nf++) {
        const int col = wn * 64 + nf * 8 + tg * 2;
        float b0 = 0.f, b1 = 0.f;
        if (add_bias) { b0 = __ldg(bias + col); b1 = __ldg(bias + col + 1); }
#pragma unroll
        for (int mf = 0; mf < 2; mf++) {
            int r = row0 + wm * 32 + mf * 16 + g;
            if (r < M) {
                float* p = C + (size_t)r * LDC + 128 + col;
                float2 v0 = make_float2(d[mf][nf][0] + b0, d[mf][nf][1] + b1);
                if (!add_bias) { float2 o = *reinterpret_cast<float2*>(p);
                                 v0.x += o.x; v0.y += o.y; }
                *reinterpret_cast<float2*>(p) = v0;
            }
            if (r + 8 < M) {
                float* p = C + (size_t)(r + 8) * LDC + 128 + col;
                float2 v1 = make_float2(d[mf][nf][2] + b0, d[mf][nf][3] + b1);
                if (!add_bias) { float2 o = *reinterpret_cast<float2*>(p);
                                 v1.x += o.x; v1.y += o.y; }
                *reinterpret_cast<float2*>(p) = v1;
            }
        }
    }
}

// ---------------------------------------------------------------------------
// prep: split W1/W2 into bf16 hi/lo  +  zero cnt and scan states
// ---------------------------------------------------------------------------
#define SPLIT_BLOCKS 96
#define ZERO_BLOCKS  196

__global__ __launch_bounds__(256)
void prep_kernel(const float* __restrict__ W1,
                 uint32_t* __restrict__ B1hi, uint32_t* __restrict__ B1lo,
                 const float* __restrict__ W2,
                 uint32_t* __restrict__ B2hi, uint32_t* __restrict__ B2lo,
                 int* __restrict__ cnt, unsigned long long* __restrict__ state,
                 int n)
{
    const int b = blockIdx.x;
    if (b < SPLIT_BLOCKS) {
        int i = b * 256 + threadIdx.x;
        const float* W; uint32_t *Bh, *Bl; int K, j;
        if (i < 128 * 64) { W = W1; Bh = g_B1hi; Bl = g_B1lo; K = 128; j = i; }
        else { W = W2; Bh = g_B2hi; Bl = g_B2lo; K = 256; j = i - 128 * 64; }
        (void)B1hi; (void)B1lo; (void)B2hi; (void)B2lo;
        int kp = j >> 7;
        int nn = j & 127;
        float w0 = W[(2 * kp) * 128 + nn];
        float w1 = W[(2 * kp + 1) * 128 + nn];
        __nv_bfloat16 h0 = __float2bfloat16_rn(w0);
        __nv_bfloat16 h1 = __float2bfloat16_rn(w1);
        __nv_bfloat16 l0 = __float2bfloat16_rn(w0 - __bfloat162float(h0));
        __nv_bfloat16 l1 = __float2bfloat16_rn(w1 - __bfloat162float(h1));
        Bh[nn * (K >> 1) + kp] = pack_bf16x2(h0, h1);
        Bl[nn * (K >> 1) + kp] = pack_bf16x2(l0, l1);
    } else {
        int i = (b - SPLIT_BLOCKS) * 256 + threadIdx.x;
        if (i <= n) cnt[i] = 0;
        if (i < SCAN_GRID) state[i] = 0ULL;
    }
}

// ---------------------------------------------------------------------------
__global__ void hist_kernel(const int* __restrict__ dst, int* __restrict__ cnt, int E)
{
    int e = blockIdx.x * blockDim.x + threadIdx.x;
    if (e < E) atomicAdd(&cnt[__ldg(dst + e)], 1);
}

// Single-pass exclusive scan with decoupled lookback (196 co-resident blocks)
__global__ __launch_bounds__(SCAN_B)
void scan_lookback_kernel(const int* __restrict__ cnt,
                          int* __restrict__ row_start, int* __restrict__ cursor,
                          unsigned long long* __restrict__ state, int n)
{
    __shared__ int ws[8];
    __shared__ int s_prefix;
    const int b    = blockIdx.x;
    const int tid  = threadIdx.x;
    const int lane = tid & 31;
    const int w    = tid >> 5;
    const int i    = b * SCAN_B + tid;

    int c = (i < n) ? cnt[i] : 0;
    int v = c;
#pragma unroll
    for (int o = 1; o < 32; o <<= 1) {
        int u = __shfl_up_sync(0xffffffffu, v, o);
        if (lane >= o) v += u;
    }
    if (lane == 31) ws[w] = v;
    __syncthreads();
    if (tid < 8) {
        int s = ws[tid];
        int t = s;
#pragma unroll
        for (int o = 1; o < 8; o <<= 1) {
            int u = __shfl_up_sync(0xffu, t, o);
            if (tid >= o) t += u;
        }
        ws[tid] = t - s;
        if (tid == 7) s_prefix = t;
    }
    __syncthreads();
    const int local_ex = ws[w] + v - c;
    const int total    = s_prefix;

    if (tid == 0) {
        int prefix = 0;
        if (b == 0) {
            atomicExch(&state[0], (2ULL << 62) | (unsigned int)total);
        } else {
            atomicExch(&state[b], (1ULL << 62) | (unsigned int)total);
            int p = b - 1;
            for (;;) {
                unsigned long long s;
                do { s = atomicAdd(&state[p], 0ULL); } while ((s >> 62) == 0ULL);
                prefix += (int)(s & 0xffffffffULL);
                if ((s >> 62) == 2ULL) break;
                p--;
            }
            atomicExch(&state[b], (2ULL << 62) | (unsigned int)(prefix + total));
        }
        s_prefix = prefix;
    }
    __syncthreads();

    if (i < n) {
        int ex = s_prefix + local_ex;
        row_start[i] = ex;
        cursor[i]    = ex;
        if (i == n - 1) row_start[n] = ex + c;
    }
}

// CSR bucket fill (standalone, light kernel: low regs, no smem)
__global__ __launch_bounds__(256)
void fill_kernel(const int* __restrict__ src, const int* __restrict__ dst,
                 int* __restrict__ cursor, int* __restrict__ edge_src, int E)
{
    int base = blockIdx.x * 1024 + threadIdx.x;
#pragma unroll
    for (int u = 0; u < 4; u++) {
        int e = base + u * 256;
        if (e < E) {
            int p = atomicAdd(&cursor[__ldg(dst + e)], 1);
            edge_src[p] = __ldg(src + e);
        }
    }
}

// ---------------------------------------------------------------------------
// Aggregation: one warp per destination node (register accumulation, 1 store)
// ---------------------------------------------------------------------------
__global__ __launch_bounds__(256)
void gather_kernel(const float* __restrict__ msg,
                   float* __restrict__ agg,
                   const int* __restrict__ row_start,
                   const int* __restrict__ edge_src,
                   int n)
{
    int w    = (blockIdx.x * blockDim.x + threadIdx.x) >> 5;
    int lane = threadIdx.x & 31;
    if (w >= n) return;

    const int start = __ldg(row_start + w);
    const int end   = __ldg(row_start + w + 1);

    const float4* mb = reinterpret_cast<const float4*>(msg);
    float4 a0 = make_float4(0.f, 0.f, 0.f, 0.f);
    float4 a1 = make_float4(0.f, 0.f, 0.f, 0.f);

    int j = start;
    for (; j + 4 <= end; j += 4) {
        int s0 = __ldg(edge_src + j);
        int s1 = __ldg(edge_src + j + 1);
        int s2 = __ldg(edge_src + j + 2);
        int s3 = __ldg(edge_src + j + 3);
        float4 v0 = __ldg(mb + (size_t)s0 * (LDC / 4) + lane);
        float4 v1 = __ldg(mb + (size_t)s1 * (LDC / 4) + lane);
        float4 v2 = __ldg(mb + (size_t)s2 * (LDC / 4) + lane);
        float4 v3 = __ldg(mb + (size_t)s3 * (LDC / 4) + lane);
        a0.x += v0.x; a0.y += v0.y; a0.z += v0.z; a0.w += v0.w;
        a1.x += v1.x; a1.y += v1.y; a1.z += v1.z; a1.w += v1.w;
        a0.x += v2.x; a0.y += v2.y; a0.z += v2.z; a0.w += v2.w;
        a1.x += v3.x; a1.y += v3.y; a1.z += v3.z; a1.w += v3.w;
    }
    for (; j < end; j++) {
        int s = __ldg(edge_src + j);
        float4 v = __ldg(mb + (size_t)s * (LDC / 4) + lane);
        a0.x += v.x; a0.y += v.y; a0.z += v.z; a0.w += v.w;
    }

    float4 r;
    r.x = a0.x + a1.x; r.y = a0.y + a1.y; r.z = a0.z + a1.z; r.w = a0.w + a1.w;
    *(reinterpret_cast<float4*>(agg) + (size_t)w * (LDC / 4) + lane) = r;
}

// ---------------------------------------------------------------------------
// Launch: two-stream DAG inside graph capture (event fork/join).
// ---------------------------------------------------------------------------
extern "C" void kernel_launch(void* const* d_in, const int* in_sizes, int n_in,
                              void* d_out, int out_size)
{
    const float* features = (const float*)d_in[0];
    const int*   src      = (const int*)  d_in[1];
    const int*   dst      = (const int*)  d_in[2];
    const float* W1       = (const float*)d_in[3];
    const float* b1       = (const float*)d_in[4];
    const float* W2       = (const float*)d_in[5];
    const float* b2       = (const float*)d_in[6];
    float*       out      = (float*)d_out;

    const int M = in_sizes[0] / 128;   // 50000
    const int E = in_sizes[1];         // 800000

    float *feat1;
    uint32_t *B1hi, *B1lo, *B2hi, *B2lo;
    int *cnt, *row_start, *cursor, *edge_src;
    unsigned long long *state;
    cudaGetSymbolAddress((void**)&feat1,     g_feat1);
    cudaGetSymbolAddress((void**)&cnt,       g_cnt);
    cudaGetSymbolAddress((void**)&row_start, g_row_start);
    cudaGetSymbolAddress((void**)&cursor,    g_cursor);
    cudaGetSymbolAddress((void**)&edge_src,  g_edge_src);
    cudaGetSymbolAddress((void**)&state,     g_scan_state);
    cudaGetSymbolAddress((void**)&B1hi,      g_B1hi);
    cudaGetSymbolAddress((void**)&B1lo,      g_B1lo);
    cudaGetSymbolAddress((void**)&B2hi,      g_B2hi);
    cudaGetSymbolAddress((void**)&B2lo,      g_B2lo);

    const int gemm_blocks   = (M + 127) / 128;              // 391
    const int edge_blocks   = (E + 255) / 256;              // 3125
    const int fill_blocks   = (E + 1023) / 1024;            // 782
    const int gather_blocks = (M + 7) / 8;                  // 6250
    const int scan_blocks   = (M + SCAN_B - 1) / SCAN_B;    // 196

    // Second stream + fork/join events (captured as graph dependencies).
    // Fallback: if creation fails, run everything on the default stream.
    cudaStream_t s2 = 0;
    cudaEvent_t evFork = nullptr, evJoin = nullptr;
    bool forked = false;
    if (cudaStreamCreateWithFlags(&s2, cudaStreamNonBlocking) == cudaSuccess &&
        cudaEventCreateWithFlags(&evFork, cudaEventDisableTiming) == cudaSuccess &&
        cudaEventCreateWithFlags(&evJoin, cudaEventDisableTiming) == cudaSuccess) {
        forked = true;
    } else {
        s2 = 0;
    }

    // L1: W split + zero cnt/scan-state  (default stream)
    prep_kernel<<<SPLIT_BLOCKS + ZERO_BLOCKS, 256>>>(W1, B1hi, B1lo, W2, B2hi, B2lo,
                                                     cnt, state, M);
    if (forked) {
        cudaEventRecord(evFork, 0);
        cudaStreamWaitEvent(s2, evFork, 0);
    }

    // Branch A (s2): CSR build chain
    hist_kernel<<<edge_blocks, 256, 0, s2>>>(dst, cnt, E);
    scan_lookback_kernel<<<scan_blocks, SCAN_B, 0, s2>>>(cnt, row_start, cursor, state, M);
    fill_kernel<<<fill_blocks, 256, 0, s2>>>(src, dst, cursor, edge_src, E);
    if (forked) cudaEventRecord(evJoin, s2);

    // Branch B (default stream): GEMM1, then m-half of GEMM2 (depends on GEMM1 only)
    gemm_tc<<<gemm_blocks, 256>>>(features, 128, B1hi, B1lo, 64, b1, feat1, M, 128);
    gemm_tc<<<gemm_blocks, 256>>>(feat1 + 128, 256, B2hi + 64, B2lo + 64, 128,
                                  b2, out, M, 128);

    // Join: gather1 needs feat1 m-half (branch B) + CSR (branch A)
    if (forked) cudaStreamWaitEvent(0, evJoin, 0);

    gather_kernel<<<gather_blocks, 256>>>(feat1 + 128, feat1, row_start, edge_src, M);

    // GEMM2 agg-half: accumulate into out[:,128:256) (bias already applied)
    gemm_tc<<<gemm_blocks, 256>>>(feat1, 256, B2hi, B2lo, 128,
                                  nullptr, out, M, 128);

    gather_kernel<<<gather_blocks, 256>>>(out + 128, out, row_start, edge_src, M);
    // (stream/events intentionally not destroyed: destroying a capturing
    //  stream is an error; kernel_launch is called O(1) times.)
}

// round 11
// speedup vs baseline: 1.2186x; 1.2186x over previous
#include <cuda_runtime.h>
#include <cuda_bf16.h>
#include <cstdint>

// ---------------------------------------------------------------------------
// GNN_85366769975686  (R10: fork CSR-chain || GEMM1 with deadlock-free scan,
//                      unsplit GEMM2, unfused light fill)
//   layer(feat, W, b): m = feat@W + b ; agg = segment_sum(m[src], dst)
//                      return concat([agg, m], -1)
// N = 50000 nodes, E = 800000 edges, D = 128, output [N, 256] fp32.
// GEMM: 3x-bf16-split m16n8k16 mma.sync (tcgen05 unusable at compute_103).
// DAG: prep -> { gemm1 (s0) } || { hist -> reduce -> scan -> down -> fill (s2) }
//      -> gather1 -> gemm2 -> gather2
// ---------------------------------------------------------------------------

#define N_MAX     50048
#define E_MAX     800000
#define LDC       256
#define SCAN_B    256
#define SCAN_GRID ((N_MAX + SCAN_B - 1) / SCAN_B)   // 196

__device__ float g_feat1[(size_t)N_MAX * LDC];
__device__ int   g_cnt[N_MAX + 1];
__device__ int   g_row_start[N_MAX + 1];
__device__ int   g_cursor[N_MAX + 1];
__device__ int   g_edge_src[E_MAX];
__device__ int   g_bsum[SCAN_GRID];
__device__ int   g_boff[SCAN_GRID];
// W split into bf16 hi/lo, packed bf16x2 along K, layout [n=128][K/2 words]
__device__ uint32_t g_B1hi[128 * 64];
__device__ uint32_t g_B1lo[128 * 64];
__device__ uint32_t g_B2hi[128 * 128];
__device__ uint32_t g_B2lo[128 * 128];

// ---------------------------------------------------------------------------
__device__ __forceinline__ uint32_t pack_bf16x2(__nv_bfloat16 lo, __nv_bfloat16 hi) {
    __nv_bfloat162 t = __halves2bfloat162(lo, hi);
    return *reinterpret_cast<uint32_t*>(&t);
}

__device__ __forceinline__ void mma_bf16(float* d, const uint32_t* a,
                                         const uint32_t b0, const uint32_t b1) {
    asm volatile(
        "mma.sync.aligned.m16n8k16.row.col.f32.bf16.bf16.f32 "
        "{%0,%1,%2,%3}, {%4,%5,%6,%7}, {%8,%9}, {%0,%1,%2,%3};"
        : "+f"(d[0]), "+f"(d[1]), "+f"(d[2]), "+f"(d[3])
        : "r"(a[0]), "r"(a[1]), "r"(a[2]), "r"(a[3]), "r"(b0), "r"(b1));
}

// ---------------------------------------------------------------------------
// 3x-bf16 mma.sync GEMM: C[row, 128+col] = sum_k A[row,k]*W[k,col] + bias[col]
// Tile 128x128, K-chunk 32; warps 4(M)x2(N); m16n8k16; APAD=20 conflict-free.
// ---------------------------------------------------------------------------
#define APAD 20
#define SM_AHI 0
#define SM_ALO (128 * APAD)
#define SM_BHI (2 * 128 * APAD)
#define SM_BLO (3 * 128 * APAD)

__global__ __launch_bounds__(256)
void gemm_tc(const float* __restrict__ A, int lda,
             const uint32_t* __restrict__ Bhi, const uint32_t* __restrict__ Blo,
             const float* __restrict__ bias,
             float* __restrict__ C, int M, int K)
{
    __shared__ uint32_t sm[4 * 128 * APAD];   // 40 KB

    const int tid  = threadIdx.x;
    const int wid  = tid >> 5;
    const int lane = tid & 31;
    const int g    = lane >> 2;
    const int tg   = lane & 3;
    const int wm   = wid & 3;
    const int wn   = wid >> 2;
    const int row0 = blockIdx.x * 128;
    const int Kw   = K >> 1;

    float d[2][8][4];
#pragma unroll
    for (int i = 0; i < 2; i++)
#pragma unroll
        for (int j = 0; j < 8; j++)
#pragma unroll
            for (int c = 0; c < 4; c++) d[i][j][c] = 0.0f;

    const int nch = K >> 5;
    for (int kc = 0; kc < nch; kc++) {
#pragma unroll
        for (int l = 0; l < 4; l++) {
            int idx = tid + l * 256;
            int row = idx >> 3;
            int c4  = idx & 7;
            int wo  = row * APAD + c4 * 2;

            int gr = row0 + row;
            float4 v = make_float4(0.f, 0.f, 0.f, 0.f);
            if (gr < M)
                v = *reinterpret_cast<const float4*>(A + (size_t)gr * lda + kc * 32 + c4 * 4);
            __nv_bfloat16 hx = __float2bfloat16_rn(v.x);
            __nv_bfloat16 hy = __float2bfloat16_rn(v.y);
            __nv_bfloat16 hz = __float2bfloat16_rn(v.z);
            __nv_bfloat16 hw = __float2bfloat16_rn(v.w);
            uint2 hv, lv;
            hv.x = pack_bf16x2(hx, hy);
            hv.y = pack_bf16x2(hz, hw);
            lv.x = pack_bf16x2(__float2bfloat16_rn(v.x - __bfloat162float(hx)),
                               __float2bfloat16_rn(v.y - __bfloat162float(hy)));
            lv.y = pack_bf16x2(__float2bfloat16_rn(v.z - __bfloat162float(hz)),
                               __float2bfloat16_rn(v.w - __bfloat162float(hw)));
            *reinterpret_cast<uint2*>(sm + SM_AHI + wo) = hv;
            *reinterpret_cast<uint2*>(sm + SM_ALO + wo) = lv;

            const size_t bofs = (size_t)row * Kw + kc * 16 + c4 * 2;
            *reinterpret_cast<uint2*>(sm + SM_BHI + wo) =
                *reinterpret_cast<const uint2*>(Bhi + bofs);
            *reinterpret_cast<uint2*>(sm + SM_BLO + wo) =
                *reinterpret_cast<const uint2*>(Blo + bofs);
        }
        __syncthreads();

#pragma unroll
        for (int ks = 0; ks < 2; ks++) {
            const int kk = ks * 8;
            uint32_t ah[2][4], al[2][4];
#pragma unroll
            for (int mf = 0; mf < 2; mf++) {
                int r0 = (wm * 32 + mf * 16 + g) * APAD + kk + tg;
                int r8 = r0 + 8 * APAD;
                ah[mf][0] = sm[SM_AHI + r0];
                ah[mf][1] = sm[SM_AHI + r8];
                ah[mf][2] = sm[SM_AHI + r0 + 4];
                ah[mf][3] = sm[SM_AHI + r8 + 4];
                al[mf][0] = sm[SM_ALO + r0];
                al[mf][1] = sm[SM_ALO + r8];
                al[mf][2] = sm[SM_ALO + r0 + 4];
                al[mf][3] = sm[SM_ALO + r8 + 4];
            }
#pragma unroll
            for (int nf = 0; nf < 8; nf++) {
                int bo = (wn * 64 + nf * 8 + g) * APAD + kk + tg;
                uint32_t bh0 = sm[SM_BHI + bo];
                uint32_t bh1 = sm[SM_BHI + bo + 4];
                uint32_t bl0 = sm[SM_BLO + bo];
                uint32_t bl1 = sm[SM_BLO + bo + 4];
#pragma unroll
                for (int mf = 0; mf < 2; mf++) {
                    mma_bf16(d[mf][nf], ah[mf], bh0, bh1);
                    mma_bf16(d[mf][nf], al[mf], bh0, bh1);
                    mma_bf16(d[mf][nf], ah[mf], bl0, bl1);
                }
            }
        }
        __syncthreads();
    }

#pragma unroll
    for (int nf = 0; nf < 8; nf++) {
        const int col = wn * 64 + nf * 8 + tg * 2;
        const float b0 = __ldg(bias + col);
        const float b1 = __ldg(bias + col + 1);
#pragma unroll
        for (int mf = 0; mf < 2; mf++) {
            int r = row0 + wm * 32 + mf * 16 + g;
            if (r < M) {
                float2 v0 = make_float2(d[mf][nf][0] + b0, d[mf][nf][1] + b1);
                *reinterpret_cast<float2*>(C + (size_t)r * LDC + 128 + col) = v0;
            }
            if (r + 8 < M) {
                float2 v1 = make_float2(d[mf][nf][2] + b0, d[mf][nf][3] + b1);
                *reinterpret_cast<float2*>(C + (size_t)(r + 8) * LDC + 128 + col) = v1;
            }
        }
    }
}

// ---------------------------------------------------------------------------
// prep: split W1/W2 into bf16 hi/lo  +  zero cnt
// ---------------------------------------------------------------------------
#define SPLIT_BLOCKS 96
#define ZERO_BLOCKS  196

__global__ __launch_bounds__(256)
void prep_kernel(const float* __restrict__ W1, const float* __restrict__ W2,
                 int* __restrict__ cnt, int n)
{
    const int b = blockIdx.x;
    if (b < SPLIT_BLOCKS) {
        int i = b * 256 + threadIdx.x;
        const float* W; uint32_t *Bh, *Bl; int K, j;
        if (i < 128 * 64) { W = W1; Bh = g_B1hi; Bl = g_B1lo; K = 128; j = i; }
        else { W = W2; Bh = g_B2hi; Bl = g_B2lo; K = 256; j = i - 128 * 64; }
        int kp = j >> 7;
        int nn = j & 127;
        float w0 = W[(2 * kp) * 128 + nn];
        float w1 = W[(2 * kp + 1) * 128 + nn];
        __nv_bfloat16 h0 = __float2bfloat16_rn(w0);
        __nv_bfloat16 h1 = __float2bfloat16_rn(w1);
        __nv_bfloat16 l0 = __float2bfloat16_rn(w0 - __bfloat162float(h0));
        __nv_bfloat16 l1 = __float2bfloat16_rn(w1 - __bfloat162float(h1));
        Bh[nn * (K >> 1) + kp] = pack_bf16x2(h0, h1);
        Bl[nn * (K >> 1) + kp] = pack_bf16x2(l0, l1);
    } else {
        int i = (b - SPLIT_BLOCKS) * 256 + threadIdx.x;
        if (i <= n) cnt[i] = 0;
    }
}

// ---------------------------------------------------------------------------
// CSR: histogram (4 edges/thread)
// ---------------------------------------------------------------------------
__global__ __launch_bounds__(256)
void hist_kernel(const int* __restrict__ dst, int* __restrict__ cnt, int E)
{
    int base = blockIdx.x * 1024 + threadIdx.x;
#pragma unroll
    for (int u = 0; u < 4; u++) {
        int e = base + u * 256;
        if (e < E) atomicAdd(&cnt[__ldg(dst + e)], 1);
    }
}

// ---------------------------------------------------------------------------
// Parallel exclusive scan — 3 phases, deadlock-free under any scheduling
// ---------------------------------------------------------------------------
__global__ __launch_bounds__(SCAN_B)
void reduce_kernel(const int* __restrict__ cnt, int* __restrict__ bsum, int n)
{
    __shared__ int ws[8];
    const int tid = threadIdx.x;
    const int i   = blockIdx.x * SCAN_B + tid;
    int v = (i < n) ? cnt[i] : 0;
#pragma unroll
    for (int o = 16; o > 0; o >>= 1) v += __shfl_down_sync(0xffffffffu, v, o);
    if ((tid & 31) == 0) ws[tid >> 5] = v;
    __syncthreads();
    if (tid < 8) {
        int s = ws[tid];
#pragma unroll
        for (int o = 4; o > 0; o >>= 1) s += __shfl_down_sync(0xffu, s, o);
        if (tid == 0) bsum[blockIdx.x] = s;
    }
}

__global__ __launch_bounds__(SCAN_B)
void scan_sums_kernel(const int* __restrict__ bsum, int* __restrict__ boff, int nb)
{
    __shared__ int ws[8];
    const int tid  = threadIdx.x;
    const int lane = tid & 31;
    const int w    = tid >> 5;
    int c = (tid < nb) ? bsum[tid] : 0;
    int v = c;
#pragma unroll
    for (int o = 1; o < 32; o <<= 1) {
        int u = __shfl_up_sync(0xffffffffu, v, o);
        if (lane >= o) v += u;
    }
    if (lane == 31) ws[w] = v;
    __syncthreads();
    if (tid < 8) {
        int s = ws[tid];
        int t = s;
#pragma unroll
        for (int o = 1; o < 8; o <<= 1) {
            int u = __shfl_up_sync(0xffu, t, o);
            if (tid >= o) t += u;
        }
        ws[tid] = t - s;
    }
    __syncthreads();
    if (tid < nb) boff[tid] = v - c + ws[w];
}

__global__ __launch_bounds__(SCAN_B)
void downsweep_kernel(const int* __restrict__ cnt, const int* __restrict__ boff,
                      int* __restrict__ row_start, int* __restrict__ cursor, int n)
{
    __shared__ int ws[8];
    const int tid  = threadIdx.x;
    const int lane = tid & 31;
    const int w    = tid >> 5;
    const int i    = blockIdx.x * SCAN_B + tid;
    int c = (i < n) ? cnt[i] : 0;
    int v = c;
#pragma unroll
    for (int o = 1; o < 32; o <<= 1) {
        int u = __shfl_up_sync(0xffffffffu, v, o);
        if (lane >= o) v += u;
    }
    if (lane == 31) ws[w] = v;
    __syncthreads();
    if (tid < 8) {
        int s = ws[tid];
        int t = s;
#pragma unroll
        for (int o = 1; o < 8; o <<= 1) {
            int u = __shfl_up_sync(0xffu, t, o);
            if (tid >= o) t += u;
        }
        ws[tid] = t - s;
    }
    __syncthreads();
    if (i < n) {
        int ex = boff[blockIdx.x] + ws[w] + v - c;
        row_start[i] = ex;
        cursor[i]    = ex;
        if (i == n - 1) row_start[n] = ex + c;
    }
}

// ---------------------------------------------------------------------------
// CSR bucket fill (light: 16 regs, no smem; 4 edges/thread)
// ---------------------------------------------------------------------------
__global__ __launch_bounds__(256)
void fill_kernel(const int* __restrict__ src, const int* __restrict__ dst,
                 int* __restrict__ cursor, int* __restrict__ edge_src, int E)
{
    int base = blockIdx.x * 1024 + threadIdx.x;
#pragma unroll
    for (int u = 0; u < 4; u++) {
        int e = base + u * 256;
        if (e < E) {
            int p = atomicAdd(&cursor[__ldg(dst + e)], 1);
            edge_src[p] = __ldg(src + e);
        }
    }
}

// ---------------------------------------------------------------------------
// Aggregation: one warp per destination node (register accumulation, 1 store)
// ---------------------------------------------------------------------------
__global__ __launch_bounds__(256)
void gather_kernel(const float* __restrict__ msg,
                   float* __restrict__ agg,
                   const int* __restrict__ row_start,
                   const int* __restrict__ edge_src,
                   int n)
{
    int w    = (blockIdx.x * blockDim.x + threadIdx.x) >> 5;
    int lane = threadIdx.x & 31;
    if (w >= n) return;

    const int start = __ldg(row_start + w);
    const int end   = __ldg(row_start + w + 1);

    const float4* mb = reinterpret_cast<const float4*>(msg);
    float4 a0 = make_float4(0.f, 0.f, 0.f, 0.f);
    float4 a1 = make_float4(0.f, 0.f, 0.f, 0.f);

    int j = start;
    for (; j + 4 <= end; j += 4) {
        int s0 = __ldg(edge_src + j);
        int s1 = __ldg(edge_src + j + 1);
        int s2 = __ldg(edge_src + j + 2);
        int s3 = __ldg(edge_src + j + 3);
        float4 v0 = __ldg(mb + (size_t)s0 * (LDC / 4) + lane);
        float4 v1 = __ldg(mb + (size_t)s1 * (LDC / 4) + lane);
        float4 v2 = __ldg(mb + (size_t)s2 * (LDC / 4) + lane);
        float4 v3 = __ldg(mb + (size_t)s3 * (LDC / 4) + lane);
        a0.x += v0.x; a0.y += v0.y; a0.z += v0.z; a0.w += v0.w;
        a1.x += v1.x; a1.y += v1.y; a1.z += v1.z; a1.w += v1.w;
        a0.x += v2.x; a0.y += v2.y; a0.z += v2.z; a0.w += v2.w;
        a1.x += v3.x; a1.y += v3.y; a1.z += v3.z; a1.w += v3.w;
    }
    for (; j < end; j++) {
        int s = __ldg(edge_src + j);
        float4 v = __ldg(mb + (size_t)s * (LDC / 4) + lane);
        a0.x += v.x; a0.y += v.y; a0.z += v.z; a0.w += v.w;
    }

    float4 r;
    r.x = a0.x + a1.x; r.y = a0.y + a1.y; r.z = a0.z + a1.z; r.w = a0.w + a1.w;
    *(reinterpret_cast<float4*>(agg) + (size_t)w * (LDC / 4) + lane) = r;
}

// ---------------------------------------------------------------------------
// Launch: fork CSR chain (deadlock-free kernels only) against GEMM1.
// ---------------------------------------------------------------------------
extern "C" void kernel_launch(void* const* d_in, const int* in_sizes, int n_in,
                              void* d_out, int out_size)
{
    const float* features = (const float*)d_in[0];
    const int*   src      = (const int*)  d_in[1];
    const int*   dst      = (const int*)  d_in[2];
    const float* W1       = (const float*)d_in[3];
    const float* b1       = (const float*)d_in[4];
    const float* W2       = (const float*)d_in[5];
    const float* b2       = (const float*)d_in[6];
    float*       out      = (float*)d_out;

    const int M = in_sizes[0] / 128;   // 50000
    const int E = in_sizes[1];         // 800000

    float *feat1;
    uint32_t *B1hi, *B1lo, *B2hi, *B2lo;
    int *cnt, *row_start, *cursor, *edge_src, *bsum, *boff;
    cudaGetSymbolAddress((void**)&feat1,     g_feat1);
    cudaGetSymbolAddress((void**)&cnt,       g_cnt);
    cudaGetSymbolAddress((void**)&row_start, g_row_start);
    cudaGetSymbolAddress((void**)&cursor,    g_cursor);
    cudaGetSymbolAddress((void**)&edge_src,  g_edge_src);
    cudaGetSymbolAddress((void**)&bsum,      g_bsum);
    cudaGetSymbolAddress((void**)&boff,      g_boff);
    cudaGetSymbolAddress((void**)&B1hi,      g_B1hi);
    cudaGetSymbolAddress((void**)&B1lo,      g_B1lo);
    cudaGetSymbolAddress((void**)&B2hi,      g_B2hi);
    cudaGetSymbolAddress((void**)&B2lo,      g_B2lo);

    const int gemm_blocks   = (M + 127) / 128;              // 391
    const int e4_blocks     = (E + 1023) / 1024;            // 782 (4 edges/thread)
    const int gather_blocks = (M + 7) / 8;                  // 6250
    const int scan_blocks   = (M + SCAN_B - 1) / SCAN_B;    // 196

    // Fork/join plumbing (captured as graph edges). Fallback: serial on s0.
    cudaStream_t s2 = 0;
    cudaEvent_t evFork = nullptr, evJoin = nullptr;
    bool forked = false;
    if (cudaStreamCreateWithFlags(&s2, cudaStreamNonBlocking) == cudaSuccess &&
        cudaEventCreateWithFlags(&evFork, cudaEventDisableTiming) == cudaSuccess &&
        cudaEventCreateWithFlags(&evJoin, cudaEventDisableTiming) == cudaSuccess) {
        forked = true;
    } else {
        s2 = 0;
    }

    // L1: W split + zero cnt
    prep_kernel<<<SPLIT_BLOCKS + ZERO_BLOCKS, 256>>>(W1, W2, cnt, M);
    if (forked) {
        cudaEventRecord(evFork, 0);
        cudaStreamWaitEvent(s2, evFork, 0);
    }

    // Branch A (s2): CSR build — all kernels deadlock-free under partial residency
    hist_kernel<<<e4_blocks, 256, 0, s2>>>(dst, cnt, E);
    reduce_kernel<<<scan_blocks, SCAN_B, 0, s2>>>(cnt, bsum, M);
    scan_sums_kernel<<<1, SCAN_B, 0, s2>>>(bsum, boff, scan_blocks);
    downsweep_kernel<<<scan_blocks, SCAN_B, 0, s2>>>(cnt, boff, row_start, cursor, M);
    fill_kernel<<<e4_blocks, 256, 0, s2>>>(src, dst, cursor, edge_src, E);
    if (forked) cudaEventRecord(evJoin, s2);

    // Branch B (s0): GEMM1
    gemm_tc<<<gemm_blocks, 256>>>(features, 128, B1hi, B1lo, b1, feat1, M, 128);

    // Join: gather1 needs m1 (B) + CSR (A)
    if (forked) cudaStreamWaitEvent(0, evJoin, 0);

    gather_kernel<<<gather_blocks, 256>>>(feat1 + 128, feat1, row_start, edge_src, M);
    gemm_tc<<<gemm_blocks, 256>>>(feat1, 256, B2hi, B2lo, b2, out, M, 256);
    gather_kernel<<<gather_blocks, 256>>>(out + 128, out, row_start, edge_src, M);
    // (stream/events not destroyed: kernel_launch is invoked O(1) times and
    //  destroying a stream that participated in capture is unsafe mid-capture.)
}